// round 17
// baseline (speedup 1.0000x reference)
#include <cuda_runtime.h>
#include <cuda_fp16.h>
#include <cstdint>

// ---------------- problem constants ----------------
#define KH 16
#define KW 16
#define Bn 64
#define Hn 1024
#define Wn 1024
#define OH 1009
#define OW 1009

// ---------------- tiling ----------------
// Block: 256 threads = 8 warps stacked in y. Block output tile 128y x 64x.
// Warp output tile 16y x 64x = 4 q-groups x 2 n-halves of m16n8.
// X and W plain fp16 (single MMA pass); measured rel_err ~3e-4.
// Manual double-buffered fragment pipeline: iter k+1's ldmatrix ops issue
// before iter k's MMA burst, hiding LDSM latency under the tensor work.
// NOTE: epilogue stores MUST be scalar STG.32 — OW=1009 is odd, so
// row*OW+col is odd for odd rows and float2 (STG.64) faults on alignment.
#define TILE_OY 128
#define TILE_OX 64
#define XROWS   143               // input rows needed: 128+15
#define XCOLS   80                // input cols needed: 64+15 (+1 spare)
#define XPITCH  88                // fp16/row -> 176B; ldmatrix conflict-free
#define XBYTES  (XROWS * XPITCH * 2)          // 25168
#define X_OFF   0
#define BW_OFF  XBYTES                        // 25168 (16B aligned)
#define BW_PITCH 40               // 80B rows; conflict-free for ldmatrix.trans
#define BW_ROWS  (16 * 16)        // ky * t = 256
#define BW_BYTES (BW_ROWS * BW_PITCH * 2)     // 20480
#define SMEM_DYN (BW_OFF + BW_BYTES)          // 45648
#define NTHREADS 256

// Precomputed Toeplitz-weight smem image (exact byte layout), built by a tiny
// pre-kernel into device scratch, then block-copied from (hot) L2.
__device__ uint4 g_bw[BW_BYTES / 16];         // 1280 x uint4

// ---------------- PTX helpers (sm_80-class; compile for compute_103) ----
__device__ __forceinline__ uint32_t smem_u32(const void* p) {
    uint32_t a;
    asm("{ .reg .u64 t; cvta.to.shared.u64 t, %1; cvt.u32.u64 %0, t; }" : "=r"(a) : "l"(p));
    return a;
}
__device__ __forceinline__ void ldsm_x4(uint32_t* r, uint32_t addr) {
    asm volatile("ldmatrix.sync.aligned.m8n8.x4.shared.b16 {%0,%1,%2,%3}, [%4];"
                 : "=r"(r[0]), "=r"(r[1]), "=r"(r[2]), "=r"(r[3]) : "r"(addr));
}
__device__ __forceinline__ void ldsm_x4_t(uint32_t* r, uint32_t addr) {
    asm volatile("ldmatrix.sync.aligned.m8n8.x4.trans.shared.b16 {%0,%1,%2,%3}, [%4];"
                 : "=r"(r[0]), "=r"(r[1]), "=r"(r[2]), "=r"(r[3]) : "r"(addr));
}
// D(16x8,f32) += A(16x16,f16 row) * B(16x8,f16 col)
__device__ __forceinline__ void mma_f16(float* d, const uint32_t* a, const uint32_t* b) {
    asm volatile(
        "mma.sync.aligned.m16n8k16.row.col.f32.f16.f16.f32 "
        "{%0,%1,%2,%3}, {%4,%5,%6,%7}, {%8,%9}, {%0,%1,%2,%3};"
        : "+f"(d[0]), "+f"(d[1]), "+f"(d[2]), "+f"(d[3])
        : "r"(a[0]), "r"(a[1]), "r"(a[2]), "r"(a[3]), "r"(b[0]), "r"(b[1]));
}

// ---------------- pre-kernel: build Toeplitz weight image (plain fp16) -----
// Row r = ky*16 + t ; col c = v*16 + n (c >= 32 is zero padding)
// Bv[t][n] = w[ky, 16v + t - n] if in range else 0
__global__ void build_bw_kernel(const float* __restrict__ kern) {
    int idx = blockIdx.x * blockDim.x + threadIdx.x;   // over BW_ROWS * BW_PITCH
    if (idx >= BW_ROWS * BW_PITCH) return;
    int r  = idx / BW_PITCH;
    int c  = idx - r * BW_PITCH;
    int ky = r >> 4;
    int t  = r & 15;
    __half val = __float2half_rn(0.0f);
    if (c < 32) {
        int v  = c >> 4;
        int n  = c & 15;
        int kx = 16 * v + t - n;
        if (kx >= 0 && kx < KW)
            val = __float2half_rn(kern[ky * KW + kx]);
    }
    reinterpret_cast<__half*>(g_bw)[idx] = val;
}

extern __shared__ char dynsm[];

__global__ __launch_bounds__(NTHREADS, 2)
void conv2d_hmma_r17_kernel(const float* __restrict__ x,
                            float* __restrict__ out)
{
    const int tid  = threadIdx.x;
    const int lane = tid & 31;
    const int wid  = tid >> 5;
    const int b    = blockIdx.z;
    const int y0   = blockIdx.y * TILE_OY;
    const int x0   = blockIdx.x * TILE_OX;

    __half* X = reinterpret_cast<__half*>(dynsm + X_OFF);

    // ---- copy Toeplitz weight image from device scratch (L2-hot) ----
    {
        uint4* dstq = reinterpret_cast<uint4*>(dynsm + BW_OFF);
        #pragma unroll
        for (int i = 0; i < BW_BYTES / 16 / NTHREADS; i++)      // 5 iters
            dstq[tid + i * NTHREADS] = g_bw[tid + i * NTHREADS];
    }

    // ---- fill X tile as fp16 (clamped reads feed only discarded outputs) ----
    const float* __restrict__ xb = x + (size_t)b * (Hn * (size_t)Wn);
    for (int idx = tid; idx < XROWS * XCOLS; idx += NTHREADS) {
        int r = idx / XCOLS;
        int c = idx - r * XCOLS;
        int gy = y0 + r; if (gy > Hn - 1) gy = Hn - 1;
        int gx = x0 + c; if (gx > Wn - 1) gx = Wn - 1;
        X[r * XPITCH + c] = __float2half_rn(xb[(size_t)gy * Wn + gx]);
    }
    __syncthreads();

    // ---- per-warp / per-lane constants ----
    const int oyw = 16 * wid;        // warp row base within tile (0..112)

    const int mat  = lane >> 3;      // ldmatrix matrix index 0..3
    const int rr   = lane & 7;
    const int grow = rr + 8 * (mat & 1);
    const int g8   = (mat >> 1) * 8;
    const uint32_t sm_base = smem_u32(dynsm);

    uint32_t a_addr = sm_base + X_OFF
                    + (uint32_t)((oyw + grow) * XPITCH + g8) * 2;
    uint32_t b_addr = sm_base + BW_OFF
                    + (uint32_t)(grow * BW_PITCH + g8) * 2;

    float acc[4][2][4];              // [q][nh][4]
    #pragma unroll
    for (int j = 0; j < 4; j++)
        #pragma unroll
        for (int k = 0; k < 2; k++)
            #pragma unroll
            for (int l = 0; l < 4; l++) acc[j][k][l] = 0.0f;

    // ---- software-pipelined ky loop (ping-pong register buffers) ----
    uint32_t Ab[2][5][4];
    uint32_t Bb[2][2][4];

    // prologue: load ky = 0
    #pragma unroll
    for (int p = 0; p < 5; p++)
        ldsm_x4(Ab[0][p], a_addr + (uint32_t)(p * 32));
    #pragma unroll
    for (int v = 0; v < 2; v++)
        ldsm_x4_t(Bb[0][v], b_addr + (uint32_t)(v * 32));

    #pragma unroll
    for (int ky = 0; ky < KH; ky++) {
        const int cur = ky & 1;
        const int nxt = cur ^ 1;
        // prefetch ky+1 fragments (independent of current MMA burst)
        if (ky + 1 < KH) {
            uint32_t a_next = a_addr + (uint32_t)((ky + 1) * XPITCH * 2);
            uint32_t b_next = b_addr + (uint32_t)((ky + 1) * 16 * BW_PITCH * 2);
            #pragma unroll
            for (int p = 0; p < 5; p++)
                ldsm_x4(Ab[nxt][p], a_next + (uint32_t)(p * 32));
            #pragma unroll
            for (int v = 0; v < 2; v++)
                ldsm_x4_t(Bb[nxt][v], b_next + (uint32_t)(v * 32));
        }
        // 16 MMAs on current buffers
        #pragma unroll
        for (int q = 0; q < 4; q++) {
            #pragma unroll
            for (int v = 0; v < 2; v++) {
                const uint32_t* a = Ab[cur][q + v];
                mma_f16(acc[q][0], a, &Bb[cur][v][0]);
                mma_f16(acc[q][1], a, &Bb[cur][v][2]);
            }
        }
    }

    // ---- epilogue: scalar stores (OW odd -> no 8B-aligned vector stores) ----
    // D frag (m16n8): d0=(g,c) d1=(g,c+1) d2=(g+8,c) d3=(g+8,c+1)
    float* __restrict__ outb = out + (size_t)b * (OH * (size_t)OW);
    const int g  = lane >> 2;
    const int c2 = (lane & 3) * 2;
    #pragma unroll
    for (int q = 0; q < 4; q++) {
        #pragma unroll
        for (int nh = 0; nh < 2; nh++) {
            const float* d = acc[q][nh];
            int row = y0 + oyw + g;
            int col = x0 + 16 * q + 8 * nh + c2;
            if (col < OW) {
                bool c1 = (col + 1 < OW);
                if (row < OH) {
                    float* po = outb + (size_t)row * OW + col;
                    po[0] = d[0];
                    if (c1) po[1] = d[1];
                }
                if (row + 8 < OH) {
                    float* po = outb + (size_t)(row + 8) * OW + col;
                    po[0] = d[2];
                    if (c1) po[1] = d[3];
                }
            }
        }
    }
}

extern "C" void kernel_launch(void* const* d_in, const int* in_sizes, int n_in,
                              void* d_out, int out_size)
{
    const float* x    = (const float*)d_in[0];   // (64, 1024, 1024) f32
    const float* kern = (const float*)d_in[1];   // (16, 16) f32
    float* out = (float*)d_out;                  // (64, 1009, 1009) f32

    // Build the Toeplitz weight image (depends only on kern; deterministic).
    build_bw_kernel<<<(BW_ROWS * BW_PITCH + 255) / 256, 256>>>(kern);

    cudaFuncSetAttribute(conv2d_hmma_r17_kernel,
                         cudaFuncAttributeMaxDynamicSharedMemorySize, SMEM_DYN);

    dim3 grid((OW + TILE_OX - 1) / TILE_OX,   // 16
              (OH + TILE_OY - 1) / TILE_OY,   // 8
              Bn);                            // 64
    conv2d_hmma_r17_kernel<<<grid, NTHREADS, SMEM_DYN>>>(x, out);
}